// round 3
// baseline (speedup 1.0000x reference)
#include <cuda_runtime.h>

// Problem shape (fixed for this problem id)
constexpr int BB = 16;
constexpr int NN = 2048;
constexpr int DD = 64;

constexpr int TM = 128;      // Q rows per block
constexpr int TN = 128;      // K cols per tile
constexpr int THREADS = 256; // 16x16 thread grid, 8x8 micro-tile each
constexpr int SQ = 132;      // Kt smem row stride (floats)
constexpr int SQD = 130;     // Qd smem row stride (ulonglong pairs)

__device__ __forceinline__ void ffma2(unsigned long long& c, unsigned long long a,
                                      unsigned long long b) {
    asm("fma.rn.f32x2 %0, %1, %2, %0;" : "+l"(c) : "l"(a), "l"(b));
}

__global__ void __launch_bounds__(THREADS, 2)
attn_argmax_kernel(const float* __restrict__ q, const float* __restrict__ kmat,
                   const float* __restrict__ v, const int* __restrict__ maski,
                   float* __restrict__ attn, float* __restrict__ outp)
{
    // Qd[k][row] holds each Q value DUPLICATED as an 8-byte (x,x) pair, so the
    // FFMA2 left operand comes straight out of LDS with no mov.b64 dup.
    __shared__ unsigned long long Qd[DD][SQD]; // 64*130*8 = 66.6 KB
    __shared__ float Kt[DD][SQ];               // transposed: Kt[k][col], 33.8 KB
    __shared__ int   finalIdx[TM];

    const int b       = blockIdx.y;
    const int rowBase = blockIdx.x * TM;
    const int tid     = threadIdx.x;
    const int tc      = tid & 15;   // col group (8 cols)
    const int tr      = tid >> 4;   // row group (8 rows)
    const int tc8     = tc * 8;
    const int tr8     = tr * 8;

    // ---- load Q tile (128 x 64), duplicated+transposed into smem ----
    {
        const float* qb = q + ((size_t)b * NN + rowBase) * DD;
        #pragma unroll
        for (int it = 0; it < 8; ++it) {
            int idx = tid + it * THREADS;   // 0..2047 float4 slots
            int r   = idx >> 4;             // row 0..127
            int c4  = idx & 15;             // float4 index within row
            float4 val = reinterpret_cast<const float4*>(qb + (size_t)r * DD)[c4];
            float vv[4] = {val.x, val.y, val.z, val.w};
            #pragma unroll
            for (int j = 0; j < 4; ++j) {
                unsigned u = __float_as_uint(vv[j]);
                unsigned long long d;
                asm("mov.b64 %0, {%1, %1};" : "=l"(d) : "r"(u));
                Qd[c4 * 4 + j][r] = d;
            }
        }
    }

    float bestVal[8];
    int   bestIdx[8];
    #pragma unroll
    for (int i = 0; i < 8; ++i) { bestVal[i] = -__int_as_float(0x7f800000); bestIdx[i] = 0; }

    for (int colBase = 0; colBase < NN; colBase += TN) {
        __syncthreads();  // Kt reuse protection (also covers Qd on iter 0)

        // ---- load K tile (128 x 64), transposed ----
        const float* kb = kmat + ((size_t)b * NN + colBase) * DD;
        #pragma unroll
        for (int it = 0; it < 8; ++it) {
            int idx = tid + it * THREADS;
            int r   = idx >> 4;
            int c4  = idx & 15;
            float4 val = reinterpret_cast<const float4*>(kb + (size_t)r * DD)[c4];
            Kt[c4 * 4 + 0][r] = val.x;
            Kt[c4 * 4 + 1][r] = val.y;
            Kt[c4 * 4 + 2][r] = val.z;
            Kt[c4 * 4 + 3][r] = val.w;
        }
        __syncthreads();

        // ---- 8x8 micro-tile GEMM with packed f32x2 FMAs (no dup movs) ----
        unsigned long long acc[8][4];
        #pragma unroll
        for (int i = 0; i < 8; ++i)
            #pragma unroll
            for (int j = 0; j < 4; ++j) acc[i][j] = 0ULL;  // (0.0f, 0.0f)

        #pragma unroll 16
        for (int kk = 0; kk < DD; ++kk) {
            const ulonglong2 ad0 = *reinterpret_cast<const ulonglong2*>(&Qd[kk][tr8]);
            const ulonglong2 ad1 = *reinterpret_cast<const ulonglong2*>(&Qd[kk][tr8 + 2]);
            const ulonglong2 ad2 = *reinterpret_cast<const ulonglong2*>(&Qd[kk][tr8 + 4]);
            const ulonglong2 ad3 = *reinterpret_cast<const ulonglong2*>(&Qd[kk][tr8 + 6]);
            const ulonglong2 bv0 = *reinterpret_cast<const ulonglong2*>(&Kt[kk][tc8]);
            const ulonglong2 bv1 = *reinterpret_cast<const ulonglong2*>(&Kt[kk][tc8 + 4]);
            unsigned long long ad[8] = {ad0.x, ad0.y, ad1.x, ad1.y,
                                        ad2.x, ad2.y, ad3.x, ad3.y};
            #pragma unroll
            for (int i = 0; i < 8; ++i) {
                ffma2(acc[i][0], ad[i], bv0.x);
                ffma2(acc[i][1], ad[i], bv0.y);
                ffma2(acc[i][2], ad[i], bv1.x);
                ffma2(acc[i][3], ad[i], bv1.y);
            }
        }

        // ---- mask + running argmax update (raw dot is argmax-equivalent) ----
        #pragma unroll
        for (int i = 0; i < 8; ++i) {
            const size_t moff =
                ((size_t)b * NN + rowBase + tr8 + i) * NN + colBase + tc8;
            const int4* mp = reinterpret_cast<const int4*>(maski + moff);
            int4 x = mp[0], y = mp[1];
            unsigned mbits =
                  (unsigned)(x.x != 0)        | ((unsigned)(x.y != 0) << 1)
                | ((unsigned)(x.z != 0) << 2) | ((unsigned)(x.w != 0) << 3)
                | ((unsigned)(y.x != 0) << 4) | ((unsigned)(y.y != 0) << 5)
                | ((unsigned)(y.z != 0) << 6) | ((unsigned)(y.w != 0) << 7);
            #pragma unroll
            for (int j = 0; j < 4; ++j) {
                float lo = __uint_as_float((unsigned)(acc[i][j] & 0xFFFFFFFFULL));
                float hi = __uint_as_float((unsigned)(acc[i][j] >> 32));
                int c0 = colBase + tc8 + 2 * j;
                if (!((mbits >> (2 * j)) & 1) && lo > bestVal[i]) { bestVal[i] = lo; bestIdx[i] = c0; }
                if (!((mbits >> (2 * j + 1)) & 1) && hi > bestVal[i]) { bestVal[i] = hi; bestIdx[i] = c0 + 1; }
            }
        }

        // ---- zero this block's attn slice for these columns (streaming) ----
        // rows [rowBase,rowBase+128) x cols [colBase,colBase+128); 2 threads/row.
        {
            int r    = tid >> 1;
            int half = tid & 1;
            float4* dst = reinterpret_cast<float4*>(
                attn + ((size_t)b * NN + rowBase + r) * NN + colBase + half * 64);
            const float4 z = make_float4(0.f, 0.f, 0.f, 0.f);
            #pragma unroll
            for (int j = 0; j < 16; ++j) __stcs(dst + j, z);
        }
    }

    // ---- cross-thread argmax reduction per row ----
    __syncthreads();  // all smem reads done; safe to reuse tiles
    float* sVal = reinterpret_cast<float*>(Qd);
    int*   sIdx = reinterpret_cast<int*>(Kt);
    #pragma unroll
    for (int i = 0; i < 8; ++i) {
        sVal[(tr8 + i) * 16 + tc] = bestVal[i];
        sIdx[(tr8 + i) * 16 + tc] = bestIdx[i];
    }
    __syncthreads();

    if (tid < TM) {
        float bv = -__int_as_float(0x7f800000);
        int   bi = 0;
        #pragma unroll
        for (int t = 0; t < 16; ++t) {
            float x = sVal[tid * 16 + t];
            if (x > bv) { bv = x; bi = sIdx[tid * 16 + t]; }
        }
        finalIdx[tid] = bi;
        // attn slice already zeroed above (ordering via __syncthreads);
        // scatter the single 1.0 per row
        attn[((size_t)b * NN + rowBase + tid) * NN + bi] = 1.0f;
    }
    __syncthreads();

    // ---- output[b, row, :] = v[b, argmax, :] (cooperative, 2 threads/row) ----
    {
        int r    = tid >> 1;
        int half = tid & 1;
        const float4* vs =
            reinterpret_cast<const float4*>(v + ((size_t)b * NN + finalIdx[r]) * DD) + half * 8;
        float4* dst =
            reinterpret_cast<float4*>(outp + ((size_t)b * NN + rowBase + r) * DD) + half * 8;
        #pragma unroll
        for (int j = 0; j < 8; ++j) dst[j] = vs[j];
    }
}

extern "C" void kernel_launch(void* const* d_in, const int* in_sizes, int n_in,
                              void* d_out, int out_size) {
    const float* q    = (const float*)d_in[0];
    const float* k    = (const float*)d_in[1];
    const float* v    = (const float*)d_in[2];
    const int*   mask = (const int*)d_in[3];

    float* attn = (float*)d_out;                      // [B, N, N]
    float* outp = attn + (size_t)BB * NN * NN;        // [B, N, D]

    dim3 grid(NN / TM, BB);
    attn_argmax_kernel<<<grid, THREADS>>>(q, k, v, mask, attn, outp);
}

// round 4
// speedup vs baseline: 1.1152x; 1.1152x over previous
#include <cuda_runtime.h>

// Problem shape (fixed for this problem id)
constexpr int BB = 16;
constexpr int NN = 2048;
constexpr int DD = 64;

constexpr int TM = 128;      // Q rows per block
constexpr int TN = 128;      // K cols per tile
constexpr int THREADS = 256; // 16x16 thread grid, 8x8 micro-tile each
constexpr int SQ = 132;      // Kt smem row stride (floats)
constexpr int SQD = 130;     // Qd smem row stride (ulonglong pairs)

__device__ __forceinline__ void ffma2(unsigned long long& c, unsigned long long a,
                                      unsigned long long b) {
    asm("fma.rn.f32x2 %0, %1, %2, %0;" : "+l"(c) : "l"(a), "l"(b));
}

__global__ void __launch_bounds__(THREADS, 2)
attn_argmax_kernel(const float* __restrict__ q, const float* __restrict__ kmat,
                   const float* __restrict__ v, const int* __restrict__ maski,
                   float* __restrict__ attn, float* __restrict__ outp)
{
    // Qd[k][row]: each Q value duplicated as an 8-byte (x,x) pair so the FFMA2
    // left operand comes straight out of LDS with no mov.b64 dup in the loop.
    __shared__ unsigned long long Qd[DD][SQD]; // 66.6 KB
    __shared__ float Kt[DD][SQ];               // transposed K, 33.8 KB
    __shared__ int   finalIdx[TM];

    const int b       = blockIdx.y;
    const int rowBase = blockIdx.x * TM;
    const int tid     = threadIdx.x;
    const int tc      = tid & 15;   // col group (8 cols)
    const int tr      = tid >> 4;   // row group (8 rows)
    const int tc8     = tc * 8;
    const int tr8     = tr * 8;

    // ---- load Q tile (128 x 64), duplicated+transposed into smem ----
    {
        const float* qb = q + ((size_t)b * NN + rowBase) * DD;
        #pragma unroll
        for (int it = 0; it < 8; ++it) {
            int idx = tid + it * THREADS;   // 0..2047 float4 slots
            int r   = idx >> 4;             // row 0..127
            int c4  = idx & 15;             // float4 index within row
            float4 val = reinterpret_cast<const float4*>(qb + (size_t)r * DD)[c4];
            float vv[4] = {val.x, val.y, val.z, val.w};
            #pragma unroll
            for (int j = 0; j < 4; ++j) {
                unsigned u = __float_as_uint(vv[j]);
                unsigned long long d;
                asm("mov.b64 %0, {%1, %1};" : "=l"(d) : "r"(u));
                Qd[c4 * 4 + j][r] = d;
            }
        }
    }

    float bestVal[8];
    int   bestIdx[8];
    #pragma unroll
    for (int i = 0; i < 8; ++i) { bestVal[i] = -__int_as_float(0x7f800000); bestIdx[i] = 0; }

    for (int colBase = 0; colBase < NN; colBase += TN) {
        __syncthreads();  // Kt reuse protection (also covers Qd on iter 0)

        // ---- load K tile (128 x 64), transposed ----
        const float* kb = kmat + ((size_t)b * NN + colBase) * DD;
        #pragma unroll
        for (int it = 0; it < 8; ++it) {
            int idx = tid + it * THREADS;
            int r   = idx >> 4;
            int c4  = idx & 15;
            float4 val = reinterpret_cast<const float4*>(kb + (size_t)r * DD)[c4];
            Kt[c4 * 4 + 0][r] = val.x;
            Kt[c4 * 4 + 1][r] = val.y;
            Kt[c4 * 4 + 2][r] = val.z;
            Kt[c4 * 4 + 3][r] = val.w;
        }
        __syncthreads();

        // ---- 8x8 micro-tile GEMM, mask loads software-pipelined into it ----
        unsigned long long acc[8][4];
        #pragma unroll
        for (int i = 0; i < 8; ++i)
            #pragma unroll
            for (int j = 0; j < 4; ++j) acc[i][j] = 0ULL;  // (0.0f, 0.0f)

        const size_t mbase = ((size_t)b * NN + rowBase + tr8) * NN + colBase + tc8;
        unsigned long long mword = 0;  // bit (8*i + j): row i, col tc8+j masked

        #pragma unroll
        for (int grp = 0; grp < 8; ++grp) {
            // issue mask loads for row `grp` now; consume after 8 kk steps
            const int4* mp = reinterpret_cast<const int4*>(maski + mbase + (size_t)grp * NN);
            int4 mx = __ldg(mp);
            int4 my = __ldg(mp + 1);

            #pragma unroll
            for (int k2 = 0; k2 < 8; ++k2) {
                const int kk = grp * 8 + k2;
                const ulonglong2 ad0 = *reinterpret_cast<const ulonglong2*>(&Qd[kk][tr8]);
                const ulonglong2 ad1 = *reinterpret_cast<const ulonglong2*>(&Qd[kk][tr8 + 2]);
                const ulonglong2 ad2 = *reinterpret_cast<const ulonglong2*>(&Qd[kk][tr8 + 4]);
                const ulonglong2 ad3 = *reinterpret_cast<const ulonglong2*>(&Qd[kk][tr8 + 6]);
                const ulonglong2 bv0 = *reinterpret_cast<const ulonglong2*>(&Kt[kk][tc8]);
                const ulonglong2 bv1 = *reinterpret_cast<const ulonglong2*>(&Kt[kk][tc8 + 4]);
                unsigned long long ad[8] = {ad0.x, ad0.y, ad1.x, ad1.y,
                                            ad2.x, ad2.y, ad3.x, ad3.y};
                #pragma unroll
                for (int i = 0; i < 8; ++i) {
                    ffma2(acc[i][0], ad[i], bv0.x);
                    ffma2(acc[i][1], ad[i], bv0.y);
                    ffma2(acc[i][2], ad[i], bv1.x);
                    ffma2(acc[i][3], ad[i], bv1.y);
                }
            }

            // fold this row's mask into 8 bits (consumed ~8 kk after issue)
            unsigned mb =
                  (unsigned)(mx.x != 0)        | ((unsigned)(mx.y != 0) << 1)
                | ((unsigned)(mx.z != 0) << 2) | ((unsigned)(mx.w != 0) << 3)
                | ((unsigned)(my.x != 0) << 4) | ((unsigned)(my.y != 0) << 5)
                | ((unsigned)(my.z != 0) << 6) | ((unsigned)(my.w != 0) << 7);
            mword |= (unsigned long long)mb << (8 * grp);
        }

        // ---- masked running argmax update (raw dot is argmax-equivalent) ----
        #pragma unroll
        for (int i = 0; i < 8; ++i) {
            const unsigned mb = (unsigned)(mword >> (8 * i)) & 0xFFu;
            #pragma unroll
            for (int j = 0; j < 4; ++j) {
                float lo = __uint_as_float((unsigned)(acc[i][j] & 0xFFFFFFFFULL));
                float hi = __uint_as_float((unsigned)(acc[i][j] >> 32));
                int c0 = colBase + tc8 + 2 * j;
                if (!((mb >> (2 * j)) & 1) && lo > bestVal[i]) { bestVal[i] = lo; bestIdx[i] = c0; }
                if (!((mb >> (2 * j + 1)) & 1) && hi > bestVal[i]) { bestVal[i] = hi; bestIdx[i] = c0 + 1; }
            }
        }
    }

    // ---- cross-thread argmax reduction per row ----
    __syncthreads();  // all smem reads done; safe to reuse tiles
    float* sVal = reinterpret_cast<float*>(Qd);
    int*   sIdx = reinterpret_cast<int*>(Kt);
    #pragma unroll
    for (int i = 0; i < 8; ++i) {
        sVal[(tr8 + i) * 16 + tc] = bestVal[i];
        sIdx[(tr8 + i) * 16 + tc] = bestIdx[i];
    }
    __syncthreads();

    if (tid < TM) {
        float bv = -__int_as_float(0x7f800000);
        int   bi = 0;
        #pragma unroll
        for (int t = 0; t < 16; ++t) {
            float x = sVal[tid * 16 + t];
            if (x > bv) { bv = x; bi = sIdx[tid * 16 + t]; }
        }
        finalIdx[tid] = bi;
        // attn pre-zeroed by memset; scatter the single 1.0 per row
        attn[((size_t)b * NN + rowBase + tid) * NN + bi] = 1.0f;
    }
    __syncthreads();

    // ---- output[b, row, :] = v[b, argmax, :] (cooperative, 2 threads/row) ----
    {
        int r    = tid >> 1;
        int half = tid & 1;
        const float4* vs =
            reinterpret_cast<const float4*>(v + ((size_t)b * NN + finalIdx[r]) * DD) + half * 8;
        float4* dst =
            reinterpret_cast<float4*>(outp + ((size_t)b * NN + rowBase + r) * DD) + half * 8;
        #pragma unroll
        for (int j = 0; j < 8; ++j) dst[j] = vs[j];
    }
}

extern "C" void kernel_launch(void* const* d_in, const int* in_sizes, int n_in,
                              void* d_out, int out_size) {
    const float* q    = (const float*)d_in[0];
    const float* k    = (const float*)d_in[1];
    const float* v    = (const float*)d_in[2];
    const int*   mask = (const int*)d_in[3];

    float* attn = (float*)d_out;                      // [B, N, N]
    float* outp = attn + (size_t)BB * NN * NN;        // [B, N, D]

    // attn is one-hot: zero-fill then scatter 1.0 per row in the kernel.
    cudaMemsetAsync(d_out, 0, (size_t)BB * NN * NN * sizeof(float));

    dim3 grid(NN / TM, BB);
    attn_argmax_kernel<<<grid, THREADS>>>(q, k, v, mask, attn, outp);
}

// round 6
// speedup vs baseline: 1.5959x; 1.4310x over previous
#include <cuda_runtime.h>
#include <cuda_bf16.h>
#include <cstdint>

constexpr int BB = 16, NN = 2048, DD = 64;
constexpr int TM = 128, TN = 128;
constexpr int THREADS = 256;          // 8 warps; warp w owns rows 16w..16w+15
constexpr int NT = NN / TN;           // 16 K-tiles
constexpr float MARG = 0.75f;         // >> 2x bf16 approx error bound
constexpr int KW = 36;                // K smem row stride in 4B words (72 bf16)

__device__ __forceinline__ uint32_t packbf(float x, float y) {
    __nv_bfloat162 h = __floats2bfloat162_rn(x, y);   // lo=x, hi=y
    return *reinterpret_cast<uint32_t*>(&h);
}

__device__ __forceinline__ void mma16816(float* c, const uint32_t* a,
                                         uint32_t b0, uint32_t b1) {
    asm volatile(
        "mma.sync.aligned.m16n8k16.row.col.f32.bf16.bf16.f32 "
        "{%0,%1,%2,%3}, {%4,%5,%6,%7}, {%8,%9}, {%0,%1,%2,%3};"
        : "+f"(c[0]), "+f"(c[1]), "+f"(c[2]), "+f"(c[3])
        : "r"(a[0]), "r"(a[1]), "r"(a[2]), "r"(a[3]), "r"(b0), "r"(b1));
}

__global__ void __launch_bounds__(THREADS, 1)
attn_hmma_kernel(const float* __restrict__ q, const float* __restrict__ kmat,
                 const float* __restrict__ v, const int* __restrict__ maski,
                 float* __restrict__ attn, float* __restrict__ outp)
{
    __shared__ __align__(16) uint32_t Ksm[TN * KW];   // bf16 K tile [n][d], 18 KB

    const int tid  = threadIdx.x;
    const int warp = tid >> 5;
    const int lane = tid & 31;
    const int g    = lane >> 2;       // 0..7
    const int tig  = lane & 3;        // 0..3
    const int b       = blockIdx.y;
    const int rowBase = blockIdx.x * TM;
    const int r0 = rowBase + warp * 16 + g;
    const int r1 = r0 + 8;

    // ---- A fragments (Q rows r0,r1 as bf16), loaded once ----
    uint32_t aF[4][4];
    {
        const float* q0 = q + ((size_t)b * NN + r0) * DD;
        const float* q1 = q + ((size_t)b * NN + r1) * DD;
        #pragma unroll
        for (int s = 0; s < 4; ++s) {
            float2 x0 = *reinterpret_cast<const float2*>(q0 + 16 * s + 2 * tig);
            float2 x1 = *reinterpret_cast<const float2*>(q1 + 16 * s + 2 * tig);
            float2 x2 = *reinterpret_cast<const float2*>(q0 + 16 * s + 2 * tig + 8);
            float2 x3 = *reinterpret_cast<const float2*>(q1 + 16 * s + 2 * tig + 8);
            aF[s][0] = packbf(x0.x, x0.y);
            aF[s][1] = packbf(x1.x, x1.y);
            aF[s][2] = packbf(x2.x, x2.y);
            aF[s][3] = packbf(x3.x, x3.y);
        }
    }

    // ---- candidate rings (shift-register, fully register-resident) ----
    float ringS0[8], ringS1[8];
    int   ringI0[8], ringI1[8];
    int   cnt0 = 0, cnt1 = 0;
    float best0 = -__int_as_float(0x7f800000), best1 = best0;

    auto insrow = [&](float (&S)[8], int (&I)[8], int& c_, float& b_, float s, int col) {
        #pragma unroll
        for (int i = 7; i > 0; --i) { S[i] = S[i - 1]; I[i] = I[i - 1]; }
        S[0] = s; I[0] = col; ++c_; if (s > b_) b_ = s;
    };

    // ---- K tile producer: thread handles row tid>>1, half (tid&1)*32 dims ----
    float4 kh[8];
    auto loadK = [&](int t) {
        const float4* src = reinterpret_cast<const float4*>(
            kmat + ((size_t)b * NN + t * TN + (tid >> 1)) * DD) + (tid & 1) * 8;
        #pragma unroll
        for (int i = 0; i < 8; ++i) kh[i] = src[i];
    };
    auto storeK = [&]() {
        uint32_t* dst = Ksm + (tid >> 1) * KW + (tid & 1) * 16;
        #pragma unroll
        for (int i = 0; i < 8; ++i) {
            uint2 p = make_uint2(packbf(kh[i].x, kh[i].y), packbf(kh[i].z, kh[i].w));
            *reinterpret_cast<uint2*>(dst + i * 2) = p;
        }
    };

    loadK(0); storeK();
    __syncthreads();

    const int* mr0 = maski + ((size_t)b * NN + r0) * NN + 2 * tig;
    const int* mr1 = maski + ((size_t)b * NN + r1) * NN + 2 * tig;

    for (int t = 0; t < NT; ++t) {
        const bool more = (t + 1 < NT);
        if (more) loadK(t + 1);   // issue gmem loads; held in regs over compute

        // ---- 64 HMMA: rows {r0,r1} x 128 cols ----
        float c[16][4];
        #pragma unroll
        for (int j = 0; j < 16; ++j)
            #pragma unroll
            for (int e = 0; e < 4; ++e) c[j][e] = 0.f;

        const uint32_t* kbase = Ksm + g * KW + tig;
        #pragma unroll
        for (int s = 0; s < 4; ++s) {
            #pragma unroll
            for (int j = 0; j < 16; ++j) {
                uint32_t b0 = kbase[j * (8 * KW) + s * 8];
                uint32_t b1 = kbase[j * (8 * KW) + s * 8 + 4];
                mma16816(c[j], aF[s], b0, b1);
            }
        }

        // ---- mask + candidate-ring update ----
        const int colBase = t * TN;
        #pragma unroll
        for (int h = 0; h < 2; ++h) {
            int2 mA[8], mB[8];
            #pragma unroll
            for (int jj = 0; jj < 8; ++jj) {
                int j = h * 8 + jj;
                mA[jj] = *reinterpret_cast<const int2*>(mr0 + colBase + 8 * j);
                mB[jj] = *reinterpret_cast<const int2*>(mr1 + colBase + 8 * j);
            }
            #pragma unroll
            for (int jj = 0; jj < 8; ++jj) {
                int j = h * 8 + jj;
                int col = colBase + 8 * j + 2 * tig;
                if (!mA[jj].x && c[j][0] >= best0 - MARG) insrow(ringS0, ringI0, cnt0, best0, c[j][0], col);
                if (!mA[jj].y && c[j][1] >= best0 - MARG) insrow(ringS0, ringI0, cnt0, best0, c[j][1], col + 1);
                if (!mB[jj].x && c[j][2] >= best1 - MARG) insrow(ringS1, ringI1, cnt1, best1, c[j][2], col);
                if (!mB[jj].y && c[j][3] >= best1 - MARG) insrow(ringS1, ringI1, cnt1, best1, c[j][3], col + 1);
            }
        }

        __syncthreads();
        if (more) { storeK(); __syncthreads(); }
    }

    // ---- exact fp32 rescore (same sequential order verified in round 2) ----
    auto finish = [&](float (&S)[8], int (&I)[8], int cnt_, float best_, int row) {
        float bE = -__int_as_float(0x7f800000);
        int   bI = 0x7fffffff;
        const int n = cnt_ < 8 ? cnt_ : 8;
        #pragma unroll
        for (int i = 0; i < 8; ++i) {
            if (i < n && S[i] >= best_ - MARG) {
                const float4* qr = reinterpret_cast<const float4*>(q + ((size_t)b * NN + row) * DD);
                const float4* kr = reinterpret_cast<const float4*>(kmat + ((size_t)b * NN + I[i]) * DD);
                float acc = 0.f;
                #pragma unroll
                for (int j2 = 0; j2 < 16; ++j2) {
                    float4 qa = qr[j2], ka = kr[j2];
                    acc = fmaf(qa.x, ka.x, acc);
                    acc = fmaf(qa.y, ka.y, acc);
                    acc = fmaf(qa.z, ka.z, acc);
                    acc = fmaf(qa.w, ka.w, acc);
                }
                if (acc > bE || (acc == bE && I[i] < bI)) { bE = acc; bI = I[i]; }
            }
        }
        #pragma unroll
        for (int off = 1; off < 4; off <<= 1) {
            float oE = __shfl_xor_sync(0xffffffffu, bE, off);
            int   oI = __shfl_xor_sync(0xffffffffu, bI, off);
            if (oE > bE || (oE == bE && oI < bI)) { bE = oE; bI = oI; }
        }
        if (bI == 0x7fffffff) bI = 0;  // safety (all-masked row: impossible here)
        if (tig == 0) attn[((size_t)b * NN + row) * NN + bI] = 1.0f;
        const float4* vs = reinterpret_cast<const float4*>(v + ((size_t)b * NN + bI) * DD);
        float4* dst = reinterpret_cast<float4*>(outp + ((size_t)b * NN + row) * DD);
        #pragma unroll
        for (int j2 = 0; j2 < 4; ++j2) dst[tig * 4 + j2] = vs[tig * 4 + j2];
    };
    finish(ringS0, ringI0, cnt0, best0, r0);
    finish(ringS1, ringI1, cnt1, best1, r1);
}

extern "C" void kernel_launch(void* const* d_in, const int* in_sizes, int n_in,
                              void* d_out, int out_size) {
    const float* q    = (const float*)d_in[0];
    const float* k    = (const float*)d_in[1];
    const float* v    = (const float*)d_in[2];
    const int*   mask = (const int*)d_in[3];

    float* attn = (float*)d_out;                   // [B, N, N]
    float* outp = attn + (size_t)BB * NN * NN;     // [B, N, D]

    // attn is one-hot: zero-fill, kernel scatters a single 1.0 per row
    cudaMemsetAsync(d_out, 0, (size_t)BB * NN * NN * sizeof(float));

    dim3 grid(NN / TM, BB);
    attn_hmma_kernel<<<grid, THREADS>>>(q, k, v, mask, attn, outp);
}

// round 8
// speedup vs baseline: 1.9795x; 1.2403x over previous
#include <cuda_runtime.h>
#include <cuda_bf16.h>
#include <cstdint>

constexpr int BB = 16, NN = 2048, DD = 64;
constexpr int TM = 128, TN = 128;
constexpr int THREADS = 256;          // 8 warps; warp w owns rows 16w..16w+15
constexpr int NT = NN / TN;           // 16 K-tiles
constexpr int KW = 36;                // K smem row stride in 4B words (72 bf16)

__device__ __forceinline__ uint32_t packbf(float x, float y) {
    __nv_bfloat162 h = __floats2bfloat162_rn(x, y);   // lo=x, hi=y
    return *reinterpret_cast<uint32_t*>(&h);
}

__device__ __forceinline__ void mma16816(float* c, const uint32_t* a,
                                         uint32_t b0, uint32_t b1) {
    asm volatile(
        "mma.sync.aligned.m16n8k16.row.col.f32.bf16.bf16.f32 "
        "{%0,%1,%2,%3}, {%4,%5,%6,%7}, {%8,%9}, {%0,%1,%2,%3};"
        : "+f"(c[0]), "+f"(c[1]), "+f"(c[2]), "+f"(c[3])
        : "r"(a[0]), "r"(a[1]), "r"(a[2]), "r"(a[3]), "r"(b0), "r"(b1));
}

constexpr unsigned NEGINF_BITS = 0xFF800000u;

// Branch-free top-4 insert of a packed (score|col) float.
// Masked entries become -inf, which falls through the sorting network
// without disturbing it (fminf(x,-inf)=-inf, fmaxf(x,-inf)=x).
__device__ __forceinline__ void top4(float (&P)[4], float s, int m, int col) {
    float pf = __int_as_float((__float_as_int(s) & 0xFFFFF800) | col);
    pf = m ? __int_as_float(NEGINF_BITS) : pf;        // SEL, branch-free
    float t1 = fminf(P[0], pf); P[0] = fmaxf(P[0], pf);
    float t2 = fminf(P[1], t1); P[1] = fmaxf(P[1], t1);
    float t3 = fminf(P[2], t2); P[2] = fmaxf(P[2], t2);
    P[3] = fmaxf(P[3], t3);
}

__global__ void __launch_bounds__(THREADS, 2)
attn_hmma_kernel(const float* __restrict__ q, const float* __restrict__ kmat,
                 const float* __restrict__ v, const int* __restrict__ maski,
                 float* __restrict__ attn, float* __restrict__ outp)
{
    __shared__ __align__(16) uint32_t Ksm[TN * KW];   // bf16 K tile [n][d], 18 KB

    const int tid  = threadIdx.x;
    const int warp = tid >> 5;
    const int lane = tid & 31;
    const int g    = lane >> 2;       // 0..7
    const int tig  = lane & 3;        // 0..3
    const int b       = blockIdx.y;
    const int rowBase = blockIdx.x * TM;
    const int r0 = rowBase + warp * 16 + g;
    const int r1 = r0 + 8;

    // ---- A fragments (Q rows r0,r1 as bf16), loaded once ----
    uint32_t aF[4][4];
    {
        const float* q0 = q + ((size_t)b * NN + r0) * DD;
        const float* q1 = q + ((size_t)b * NN + r1) * DD;
        #pragma unroll
        for (int s = 0; s < 4; ++s) {
            float2 x0 = *reinterpret_cast<const float2*>(q0 + 16 * s + 2 * tig);
            float2 x1 = *reinterpret_cast<const float2*>(q1 + 16 * s + 2 * tig);
            float2 x2 = *reinterpret_cast<const float2*>(q0 + 16 * s + 2 * tig + 8);
            float2 x3 = *reinterpret_cast<const float2*>(q1 + 16 * s + 2 * tig + 8);
            aF[s][0] = packbf(x0.x, x0.y);
            aF[s][1] = packbf(x1.x, x1.y);
            aF[s][2] = packbf(x2.x, x2.y);
            aF[s][3] = packbf(x3.x, x3.y);
        }
    }

    const float NEGINF = __int_as_float(NEGINF_BITS);
    float p0[4] = {NEGINF, NEGINF, NEGINF, NEGINF};   // packed top-4, row r0
    float p1[4] = {NEGINF, NEGINF, NEGINF, NEGINF};   // packed top-4, row r1

    const int* mr0 = maski + ((size_t)b * NN + r0) * NN + 2 * tig;
    const int* mr1 = maski + ((size_t)b * NN + r1) * NN + 2 * tig;

    for (int t = 0; t < NT; ++t) {
        if (t) __syncthreads();   // prior tile fully consumed before overwrite

        // ---- load + convert K tile (row = tid>>1, d-half = (tid&1)*32) ----
        {
            const float4* src = reinterpret_cast<const float4*>(
                kmat + ((size_t)b * NN + t * TN + (tid >> 1)) * DD) + (tid & 1) * 8;
            uint32_t* dst = Ksm + (tid >> 1) * KW + (tid & 1) * 16;
            #pragma unroll
            for (int qt = 0; qt < 2; ++qt) {
                float4 f0 = src[qt * 4 + 0], f1 = src[qt * 4 + 1];
                float4 f2 = src[qt * 4 + 2], f3 = src[qt * 4 + 3];
                uint4 w0 = make_uint4(packbf(f0.x, f0.y), packbf(f0.z, f0.w),
                                      packbf(f1.x, f1.y), packbf(f1.z, f1.w));
                uint4 w1 = make_uint4(packbf(f2.x, f2.y), packbf(f2.z, f2.w),
                                      packbf(f3.x, f3.y), packbf(f3.z, f3.w));
                *reinterpret_cast<uint4*>(dst + qt * 8)     = w0;
                *reinterpret_cast<uint4*>(dst + qt * 8 + 4) = w1;
            }
        }
        __syncthreads();

        // ---- per j-half: 32 HMMA + branch-free epilogue ----
        #pragma unroll
        for (int jh = 0; jh < 2; ++jh) {
            float c[8][4];
            #pragma unroll
            for (int j = 0; j < 8; ++j)
                #pragma unroll
                for (int e = 0; e < 4; ++e) c[j][e] = 0.f;

            const uint32_t* kbase = Ksm + g * KW + tig + jh * 8 * (8 * KW);
            #pragma unroll
            for (int s = 0; s < 4; ++s) {
                #pragma unroll
                for (int j = 0; j < 8; ++j) {
                    uint32_t b0 = kbase[j * (8 * KW) + s * 8];
                    uint32_t b1 = kbase[j * (8 * KW) + s * 8 + 4];
                    mma16816(c[j], aF[s], b0, b1);
                }
            }

            const int colBase = t * TN + jh * 64;
            int2 mA[8], mB[8];
            #pragma unroll
            for (int jj = 0; jj < 8; ++jj) {
                mA[jj] = __ldcs(reinterpret_cast<const int2*>(mr0 + colBase + 8 * jj));
                mB[jj] = __ldcs(reinterpret_cast<const int2*>(mr1 + colBase + 8 * jj));
            }
            #pragma unroll
            for (int jj = 0; jj < 8; ++jj) {
                const int col = colBase + 8 * jj + 2 * tig;
                top4(p0, c[jj][0], mA[jj].x, col);
                top4(p0, c[jj][1], mA[jj].y, col + 1);
                top4(p1, c[jj][2], mB[jj].x, col);
                top4(p1, c[jj][3], mB[jj].y, col + 1);
            }
        }
    }

    // ---- exact fp32 rescore of <=4 candidates/lane (round-2-verified order) ----
    auto finish = [&](float (&P)[4], int row) {
        float bE = -__int_as_float(0x7f800000);
        int   bI = 0x7fffffff;
        #pragma unroll
        for (int i = 0; i < 4; ++i) {
            if (P[i] != NEGINF) {
                const int cI = __float_as_int(P[i]) & 0x7FF;
                const float4* qr = reinterpret_cast<const float4*>(q + ((size_t)b * NN + row) * DD);
                const float4* kr = reinterpret_cast<const float4*>(kmat + ((size_t)b * NN + cI) * DD);
                float acc = 0.f;
                #pragma unroll
                for (int j2 = 0; j2 < 16; ++j2) {
                    float4 qa = qr[j2], ka = kr[j2];
                    acc = fmaf(qa.x, ka.x, acc);
                    acc = fmaf(qa.y, ka.y, acc);
                    acc = fmaf(qa.z, ka.z, acc);
                    acc = fmaf(qa.w, ka.w, acc);
                }
                if (acc > bE || (acc == bE && cI < bI)) { bE = acc; bI = cI; }
            }
        }
        #pragma unroll
        for (int off = 1; off < 4; off <<= 1) {
            float oE = __shfl_xor_sync(0xffffffffu, bE, off);
            int   oI = __shfl_xor_sync(0xffffffffu, bI, off);
            if (oE > bE || (oE == bE && oI < bI)) { bE = oE; bI = oI; }
        }
        if (bI == 0x7fffffff) bI = 0;  // safety (all-masked row: impossible here)
        if (tig == 0) attn[((size_t)b * NN + row) * NN + bI] = 1.0f;
        const float4* vs = reinterpret_cast<const float4*>(v + ((size_t)b * NN + bI) * DD);
        float4* dst = reinterpret_cast<float4*>(outp + ((size_t)b * NN + row) * DD);
        #pragma unroll
        for (int j2 = 0; j2 < 4; ++j2) dst[tig * 4 + j2] = vs[tig * 4 + j2];
    };
    finish(p0, r0);
    finish(p1, r1);
}

extern "C" void kernel_launch(void* const* d_in, const int* in_sizes, int n_in,
                              void* d_out, int out_size) {
    const float* q    = (const float*)d_in[0];
    const float* k    = (const float*)d_in[1];
    const float* v    = (const float*)d_in[2];
    const int*   mask = (const int*)d_in[3];

    float* attn = (float*)d_out;                   // [B, N, N]
    float* outp = attn + (size_t)BB * NN * NN;     // [B, N, D]

    // attn is one-hot: zero-fill, kernel scatters a single 1.0 per row
    cudaMemsetAsync(d_out, 0, (size_t)BB * NN * NN * sizeof(float));

    dim3 grid(NN / TM, BB);
    attn_hmma_kernel<<<grid, THREADS>>>(q, k, v, mask, attn, outp);
}

// round 9
// speedup vs baseline: 2.0210x; 1.0210x over previous
#include <cuda_runtime.h>
#include <cuda_bf16.h>
#include <cstdint>

constexpr int BB = 16, NN = 2048, DD = 64;
constexpr int TM = 128, TN = 128;
constexpr int THREADS = 256;          // 8 warps; warp w owns rows 16w..16w+15
constexpr int NT = NN / TN;           // 16 K-tiles
constexpr int KW = 36;                // K smem row stride in 4B words (72 bf16)

__device__ __forceinline__ uint32_t packbf(float x, float y) {
    __nv_bfloat162 h = __floats2bfloat162_rn(x, y);   // lo=x, hi=y
    return *reinterpret_cast<uint32_t*>(&h);
}

__device__ __forceinline__ void mma16816(float* c, const uint32_t* a,
                                         uint32_t b0, uint32_t b1) {
    asm volatile(
        "mma.sync.aligned.m16n8k16.row.col.f32.bf16.bf16.f32 "
        "{%0,%1,%2,%3}, {%4,%5,%6,%7}, {%8,%9}, {%0,%1,%2,%3};"
        : "+f"(c[0]), "+f"(c[1]), "+f"(c[2]), "+f"(c[3])
        : "r"(a[0]), "r"(a[1]), "r"(a[2]), "r"(a[3]), "r"(b0), "r"(b1));
}

__device__ __forceinline__ void ldsm_x4(uint32_t& f0, uint32_t& f1,
                                        uint32_t& f2, uint32_t& f3, uint32_t addr) {
    asm volatile("ldmatrix.sync.aligned.m8n8.x4.shared.b16 {%0,%1,%2,%3}, [%4];"
                 : "=r"(f0), "=r"(f1), "=r"(f2), "=r"(f3) : "r"(addr));
}

constexpr unsigned NEGINF_BITS = 0xFF800000u;

// Branch-free top-4 insert of a packed (score|col) float.
// Masked entries become -inf, falling through the network harmlessly.
__device__ __forceinline__ void top4(float (&P)[4], float s, int m, int col) {
    float pf = __int_as_float((__float_as_int(s) & 0xFFFFF800) | col);
    pf = m ? __int_as_float(NEGINF_BITS) : pf;        // SEL, branch-free
    float t1 = fminf(P[0], pf); P[0] = fmaxf(P[0], pf);
    float t2 = fminf(P[1], t1); P[1] = fmaxf(P[1], t1);
    float t3 = fminf(P[2], t2); P[2] = fmaxf(P[2], t2);
    P[3] = fmaxf(P[3], t3);
}

__global__ void __launch_bounds__(THREADS, 2)
attn_hmma_kernel(const float* __restrict__ q, const float* __restrict__ kmat,
                 const float* __restrict__ v, const int* __restrict__ maski,
                 float* __restrict__ attn, float* __restrict__ outp)
{
    __shared__ __align__(16) uint32_t Ksm[TN * KW];   // bf16 K tile [n][d], 18 KB

    const int tid  = threadIdx.x;
    const int warp = tid >> 5;
    const int lane = tid & 31;
    const int g    = lane >> 2;       // 0..7
    const int tig  = lane & 3;        // 0..3
    const int b       = blockIdx.y;
    const int rowBase = blockIdx.x * TM;
    const int r0 = rowBase + warp * 16 + g;
    const int r1 = r0 + 8;

    // ldmatrix per-lane base: matrix m = lane>>3, row r = lane&7
    uint32_t sKsm;
    asm("{ .reg .u64 t; cvta.to.shared.u64 t, %1; cvt.u32.u64 %0, t; }"
        : "=r"(sKsm) : "l"(Ksm));
    const int lm_m  = lane >> 3;
    const int lm_r  = lane & 7;
    const uint32_t lmBase = sKsm + 4u * ((uint32_t)(8 * (lm_m >> 1) + lm_r) * KW
                                         + (uint32_t)(lm_m & 1) * 4u);

    // ---- A fragments (Q rows r0,r1 as bf16), loaded once ----
    uint32_t aF[4][4];
    {
        const float* q0 = q + ((size_t)b * NN + r0) * DD;
        const float* q1 = q + ((size_t)b * NN + r1) * DD;
        #pragma unroll
        for (int s = 0; s < 4; ++s) {
            float2 x0 = *reinterpret_cast<const float2*>(q0 + 16 * s + 2 * tig);
            float2 x1 = *reinterpret_cast<const float2*>(q1 + 16 * s + 2 * tig);
            float2 x2 = *reinterpret_cast<const float2*>(q0 + 16 * s + 2 * tig + 8);
            float2 x3 = *reinterpret_cast<const float2*>(q1 + 16 * s + 2 * tig + 8);
            aF[s][0] = packbf(x0.x, x0.y);
            aF[s][1] = packbf(x1.x, x1.y);
            aF[s][2] = packbf(x2.x, x2.y);
            aF[s][3] = packbf(x3.x, x3.y);
        }
    }

    const float NEGINF = __int_as_float(NEGINF_BITS);
    float p0[4] = {NEGINF, NEGINF, NEGINF, NEGINF};
    float p1[4] = {NEGINF, NEGINF, NEGINF, NEGINF};

    const int* mr0 = maski + ((size_t)b * NN + r0) * NN + 2 * tig;
    const int* mr1 = maski + ((size_t)b * NN + r1) * NN + 2 * tig;

    for (int t = 0; t < NT; ++t) {
        if (t) __syncthreads();   // prior tile fully consumed before overwrite

        // ---- load + convert K tile (row = tid>>1, d-half = (tid&1)*32) ----
        {
            const float4* src = reinterpret_cast<const float4*>(
                kmat + ((size_t)b * NN + t * TN + (tid >> 1)) * DD) + (tid & 1) * 8;
            uint32_t* dst = Ksm + (tid >> 1) * KW + (tid & 1) * 16;
            #pragma unroll
            for (int qt = 0; qt < 2; ++qt) {
                float4 f0 = src[qt * 4 + 0], f1 = src[qt * 4 + 1];
                float4 f2 = src[qt * 4 + 2], f3 = src[qt * 4 + 3];
                uint4 w0 = make_uint4(packbf(f0.x, f0.y), packbf(f0.z, f0.w),
                                      packbf(f1.x, f1.y), packbf(f1.z, f1.w));
                uint4 w1 = make_uint4(packbf(f2.x, f2.y), packbf(f2.z, f2.w),
                                      packbf(f3.x, f3.y), packbf(f3.z, f3.w));
                *reinterpret_cast<uint4*>(dst + qt * 8)     = w0;
                *reinterpret_cast<uint4*>(dst + qt * 8 + 4) = w1;
            }
        }
        __syncthreads();

        #pragma unroll
        for (int jh = 0; jh < 2; ++jh) {
            const int colBase = t * TN + jh * 64;

            // ---- mask loads FIRST: latency hidden under LDSM+HMMA below ----
            int2 mA[8], mB[8];
            #pragma unroll
            for (int jj = 0; jj < 8; ++jj) {
                mA[jj] = __ldcs(reinterpret_cast<const int2*>(mr0 + colBase + 8 * jj));
                mB[jj] = __ldcs(reinterpret_cast<const int2*>(mr1 + colBase + 8 * jj));
            }

            // ---- 16 ldmatrix.x4 + 32 HMMA ----
            float c[8][4];
            #pragma unroll
            for (int j = 0; j < 8; ++j)
                #pragma unroll
                for (int e = 0; e < 4; ++e) c[j][e] = 0.f;

            #pragma unroll
            for (int jp = 0; jp < 4; ++jp) {
                const uint32_t aj = lmBase + 4u * (uint32_t)((64 * jh + 16 * jp) * KW);
                #pragma unroll
                for (int s = 0; s < 4; ++s) {
                    uint32_t f0, f1, f2, f3;
                    ldsm_x4(f0, f1, f2, f3, aj + 32u * s);
                    mma16816(c[2 * jp],     aF[s], f0, f1);
                    mma16816(c[2 * jp + 1], aF[s], f2, f3);
                }
            }

            // ---- branch-free top-4 update ----
            #pragma unroll
            for (int jj = 0; jj < 8; ++jj) {
                const int col = colBase + 8 * jj + 2 * tig;
                top4(p0, c[jj][0], mA[jj].x, col);
                top4(p0, c[jj][1], mA[jj].y, col + 1);
                top4(p1, c[jj][2], mB[jj].x, col);
                top4(p1, c[jj][3], mB[jj].y, col + 1);
            }
        }
    }

    // ---- exact fp32 rescore of <=4 candidates/lane (round-2-verified order) ----
    auto finish = [&](float (&P)[4], int row) {
        float bE = -__int_as_float(0x7f800000);
        int   bI = 0x7fffffff;
        #pragma unroll
        for (int i = 0; i < 4; ++i) {
            if (P[i] != NEGINF) {
                const int cI = __float_as_int(P[i]) & 0x7FF;
                const float4* qr = reinterpret_cast<const float4*>(q + ((size_t)b * NN + row) * DD);
                const float4* kr = reinterpret_cast<const float4*>(kmat + ((size_t)b * NN + cI) * DD);
                float acc = 0.f;
                #pragma unroll
                for (int j2 = 0; j2 < 16; ++j2) {
                    float4 qa = qr[j2], ka = kr[j2];
                    acc = fmaf(qa.x, ka.x, acc);
                    acc = fmaf(qa.y, ka.y, acc);
                    acc = fmaf(qa.z, ka.z, acc);
                    acc = fmaf(qa.w, ka.w, acc);
                }
                if (acc > bE || (acc == bE && cI < bI)) { bE = acc; bI = cI; }
            }
        }
        #pragma unroll
        for (int off = 1; off < 4; off <<= 1) {
            float oE = __shfl_xor_sync(0xffffffffu, bE, off);
            int   oI = __shfl_xor_sync(0xffffffffu, bI, off);
            if (oE > bE || (oE == bE && oI < bI)) { bE = oE; bI = oI; }
        }
        if (bI == 0x7fffffff) bI = 0;  // safety (all-masked row: impossible here)
        if (tig == 0) attn[((size_t)b * NN + row) * NN + bI] = 1.0f;
        const float4* vs = reinterpret_cast<const float4*>(v + ((size_t)b * NN + bI) * DD);
        float4* dst = reinterpret_cast<float4*>(outp + ((size_t)b * NN + row) * DD);
        #pragma unroll
        for (int j2 = 0; j2 < 4; ++j2) dst[tig * 4 + j2] = vs[tig * 4 + j2];
    };
    finish(p0, r0);
    finish(p1, r1);
}

extern "C" void kernel_launch(void* const* d_in, const int* in_sizes, int n_in,
                              void* d_out, int out_size) {
    const float* q    = (const float*)d_in[0];
    const float* k    = (const float*)d_in[1];
    const float* v    = (const float*)d_in[2];
    const int*   mask = (const int*)d_in[3];

    float* attn = (float*)d_out;                   // [B, N, N]
    float* outp = attn + (size_t)BB * NN * NN;     // [B, N, D]

    // attn is one-hot: zero-fill, kernel scatters a single 1.0 per row
    cudaMemsetAsync(d_out, 0, (size_t)BB * NN * NN * sizeof(float));

    dim3 grid(NN / TM, BB);
    attn_hmma_kernel<<<grid, THREADS>>>(q, k, v, mask, attn, outp);
}